// round 1
// baseline (speedup 1.0000x reference)
#include <cuda_runtime.h>
#include <math.h>

#define NN 50000
#define NE 800000
#define FIN 64
#define DD 128
#define NL 3
#define NB 8
#define POOL_C 64

// ---------------- scratch (device globals; no allocation) ----------------
__device__ float g_h[NN * DD];
__device__ float g_z[NN * DD];
__device__ float g_agg[NN * DD];
__device__ int   g_cnt[NN];
__device__ int   g_rowptr[NN + 1];
__device__ int   g_cursor[NN];
__device__ int   g_col[NE];
__device__ float g_deg[NN];
__device__ float g_logit[NN];
__device__ float g_gate[NN];
__device__ float g_red[512];
__device__ float g_consts[2];
__device__ int   g_bstart[NB + 1];
__device__ float g_pool_part[NB * POOL_C * DD];
__device__ float g_pooled[NB * DD];

// ---------------- helpers ----------------
__device__ __forceinline__ float geluf(float x) {
    return 0.5f * x * (1.0f + erff(x * 0.7071067811865476f));
}
__device__ __forceinline__ float wsum(float v) {
#pragma unroll
    for (int o = 16; o > 0; o >>= 1) v += __shfl_xor_sync(0xffffffffu, v, o);
    return v;
}
__device__ __forceinline__ float wmax(float v) {
#pragma unroll
    for (int o = 16; o > 0; o >>= 1) v = fmaxf(v, __shfl_xor_sync(0xffffffffu, v, o));
    return v;
}
// LayerNorm over a 128-wide row held as one float4 per lane (warp-collective)
__device__ __forceinline__ float4 ln128(float4 v, const float* __restrict__ g,
                                        const float* __restrict__ b, int lane) {
    float m = wsum(v.x + v.y + v.z + v.w) * (1.0f / 128.0f);
    float dx = v.x - m, dy = v.y - m, dz = v.z - m, dw = v.w - m;
    float var = wsum(dx * dx + dy * dy + dz * dz + dw * dw) * (1.0f / 128.0f);
    float rs = rsqrtf(var + 1e-5f);
    float4 gg = *reinterpret_cast<const float4*>(g + lane * 4);
    float4 bb = *reinterpret_cast<const float4*>(b + lane * 4);
    return make_float4(dx * rs * gg.x + bb.x, dy * rs * gg.y + bb.y,
                       dz * rs * gg.z + bb.z, dw * rs * gg.w + bb.w);
}

// ---------------- CSR build ----------------
__global__ void k_zero() {
    int i = blockIdx.x * blockDim.x + threadIdx.x;
    if (i < NN) g_cnt[i] = 0;
}
__global__ void k_count(const int* __restrict__ ei) {
    int e = blockIdx.x * blockDim.x + threadIdx.x;
    if (e < NE) atomicAdd(&g_cnt[ei[NE + e]], 1);
}
__global__ void k_scan() {
    __shared__ int sh_warp[32];
    __shared__ int sh_carry;
    int t = threadIdx.x;
    if (t == 0) { sh_carry = 0; g_rowptr[0] = 0; }
    __syncthreads();
    for (int base = 0; base < NN; base += 1024) {
        int i = base + t;
        int v = (i < NN) ? g_cnt[i] : 0;
        int x = v;
#pragma unroll
        for (int o = 1; o < 32; o <<= 1) {
            int y = __shfl_up_sync(0xffffffffu, x, o);
            if ((t & 31) >= o) x += y;
        }
        if ((t & 31) == 31) sh_warp[t >> 5] = x;
        __syncthreads();
        if (t < 32) {
            int w = sh_warp[t];
#pragma unroll
            for (int o = 1; o < 32; o <<= 1) {
                int y = __shfl_up_sync(0xffffffffu, w, o);
                if (t >= o) w += y;
            }
            sh_warp[t] = w;
        }
        __syncthreads();
        int pre = (t >= 32) ? sh_warp[(t >> 5) - 1] : 0;
        int incl = x + pre + sh_carry;
        if (i < NN) {
            g_rowptr[i + 1] = incl;
            g_cursor[i] = incl - v;
            g_deg[i] = (v > 0) ? (float)v : 1.0f;
        }
        __syncthreads();
        if (t == 1023) sh_carry = incl;
        __syncthreads();
    }
}
__global__ void k_scatter(const int* __restrict__ ei) {
    int e = blockIdx.x * blockDim.x + threadIdx.x;
    if (e < NE) {
        int d = ei[NE + e];
        int p = atomicAdd(&g_cursor[d], 1);
        g_col[p] = ei[e];
    }
}

// ---------------- tiled fp32 GEMM: out = A @ W + bias  (writes g_z) ----------------
// A is [nrows, KD] (for KD==256: concat of A0[.,128] and A1[.,128]); W is [KD,128].
// EPI: 0 = none, 1 = tanh.
template <int KD, int EPI>
__global__ void __launch_bounds__(256) gemm_k(const float* __restrict__ A0,
                                              const float* __restrict__ A1,
                                              const float* __restrict__ W,
                                              const float* __restrict__ bias,
                                              int nrows) {
    __shared__ float As[8][132];
    __shared__ float Bs[8][128];
    const int t = threadIdx.x;
    const int row0 = blockIdx.x * 128;
    const int a_r = t >> 1;
    const int a_k = (t & 1) * 4;
    const int b_k = t >> 5;
    const int b_n = (t & 31) * 4;
    const int ty = t >> 4;
    const int tx = t & 15;
    constexpr int STRIDE = (KD == 256) ? 128 : KD;
    float acc[8][8];
#pragma unroll
    for (int i = 0; i < 8; i++)
#pragma unroll
        for (int j = 0; j < 8; j++) acc[i][j] = 0.0f;
    const int gr = row0 + a_r;
    for (int k0 = 0; k0 < KD; k0 += 8) {
        float4 av = make_float4(0.f, 0.f, 0.f, 0.f);
        if (gr < nrows) {
            int kk = k0 + a_k;
            const float* Ap = A0;
            if (KD == 256 && kk >= 128) { Ap = A1; kk -= 128; }
            av = *reinterpret_cast<const float4*>(Ap + (size_t)gr * STRIDE + kk);
        }
        As[a_k + 0][a_r] = av.x;
        As[a_k + 1][a_r] = av.y;
        As[a_k + 2][a_r] = av.z;
        As[a_k + 3][a_r] = av.w;
        *reinterpret_cast<float4*>(&Bs[b_k][b_n]) =
            *reinterpret_cast<const float4*>(W + (size_t)(k0 + b_k) * 128 + b_n);
        __syncthreads();
#pragma unroll
        for (int k = 0; k < 8; k++) {
            float a[8], b[8];
            *reinterpret_cast<float4*>(a)     = *reinterpret_cast<const float4*>(&As[k][ty * 8]);
            *reinterpret_cast<float4*>(a + 4) = *reinterpret_cast<const float4*>(&As[k][ty * 8 + 4]);
            *reinterpret_cast<float4*>(b)     = *reinterpret_cast<const float4*>(&Bs[k][tx * 8]);
            *reinterpret_cast<float4*>(b + 4) = *reinterpret_cast<const float4*>(&Bs[k][tx * 8 + 4]);
#pragma unroll
            for (int i = 0; i < 8; i++)
#pragma unroll
                for (int j = 0; j < 8; j++) acc[i][j] += a[i] * b[j];
        }
        __syncthreads();
    }
    float bb[8];
#pragma unroll
    for (int j = 0; j < 8; j++) bb[j] = bias[tx * 8 + j];
#pragma unroll
    for (int i = 0; i < 8; i++) {
        int r = row0 + ty * 8 + i;
        if (r < nrows) {
            float o[8];
#pragma unroll
            for (int j = 0; j < 8; j++) {
                float v = acc[i][j] + bb[j];
                if (EPI == 1) v = tanhf(v);
                o[j] = v;
            }
            *reinterpret_cast<float4*>(g_z + (size_t)r * 128 + tx * 8) =
                make_float4(o[0], o[1], o[2], o[3]);
            *reinterpret_cast<float4*>(g_z + (size_t)r * 128 + tx * 8 + 4) =
                make_float4(o[4], o[5], o[6], o[7]);
        }
    }
}

// ---------------- elementwise: h = gelu(ln(z)) ----------------
__global__ void k_ln_gelu(const float* __restrict__ g, const float* __restrict__ b) {
    int gid = blockIdx.x * blockDim.x + threadIdx.x;
    int node = gid >> 5, lane = gid & 31;
    if (node >= NN) return;
    float4 z = *reinterpret_cast<const float4*>(g_z + (size_t)node * DD + lane * 4);
    float4 u = ln128(z, g, b, lane);
    u.x = geluf(u.x); u.y = geluf(u.y); u.z = geluf(u.z); u.w = geluf(u.w);
    *reinterpret_cast<float4*>(g_h + (size_t)node * DD + lane * 4) = u;
}

// ---------------- aggregation: agg = mean over CSR neighbors ----------------
__global__ void k_aggregate() {
    int gid = blockIdx.x * blockDim.x + threadIdx.x;
    int node = gid >> 5, lane = gid & 31;
    if (node >= NN) return;
    int s = g_rowptr[node], e = g_rowptr[node + 1];
    float4 acc = make_float4(0.f, 0.f, 0.f, 0.f);
    const float4* h4 = reinterpret_cast<const float4*>(g_h);
    for (int i = s; i < e; i++) {
        int src = g_col[i];
        float4 v = h4[(size_t)src * 32 + lane];
        acc.x += v.x; acc.y += v.y; acc.z += v.z; acc.w += v.w;
    }
    float inv = 1.0f / g_deg[node];
    acc.x *= inv; acc.y *= inv; acc.z *= inv; acc.w *= inv;
    reinterpret_cast<float4*>(g_agg)[(size_t)node * 32 + lane] = acc;
}

// ---------------- per-layer post: gelu -> LN(gnn_ln) -> LN(norm) [-> gelu + residual] ----------------
__global__ void k_layer_post(const float* __restrict__ g1, const float* __restrict__ b1,
                             const float* __restrict__ g2, const float* __restrict__ b2,
                             int residual, float* __restrict__ out_h) {
    int gid = blockIdx.x * blockDim.x + threadIdx.x;
    int node = gid >> 5, lane = gid & 31;
    if (node >= NN) return;
    float4 z = *reinterpret_cast<const float4*>(g_z + (size_t)node * DD + lane * 4);
    float4 t = make_float4(geluf(z.x), geluf(z.y), geluf(z.z), geluf(z.w));
    float4 u = ln128(t, g1, b1, lane);
    float4 w = ln128(u, g2, b2, lane);
    float4 r = w;
    if (residual) {
        float4 ho = *reinterpret_cast<const float4*>(g_h + (size_t)node * DD + lane * 4);
        r.x = geluf(w.x) + ho.x;
        r.y = geluf(w.y) + ho.y;
        r.z = geluf(w.z) + ho.z;
        r.w = geluf(w.w) + ho.w;
    }
    *reinterpret_cast<float4*>(g_h + (size_t)node * DD + lane * 4) = r;
    if (out_h)
        *reinterpret_cast<float4*>(out_h + (size_t)node * DD + lane * 4) = r;
}

// ---------------- gate logits: dot(tanh_hidden_row, w2) + b2 ----------------
__global__ void k_logits(const float* __restrict__ w2, const float* __restrict__ b2) {
    int gid = blockIdx.x * blockDim.x + threadIdx.x;
    int node = gid >> 5, lane = gid & 31;
    if (node >= NN) return;
    float4 h4 = reinterpret_cast<const float4*>(g_z)[(size_t)node * 32 + lane];
    float4 w4 = reinterpret_cast<const float4*>(w2)[lane];
    float p = h4.x * w4.x + h4.y * w4.y + h4.z * w4.z + h4.w * w4.w;
    p = wsum(p);
    if (lane == 0) g_logit[node] = p + b2[0];
}

// ---------------- softmax reductions ----------------
__global__ void k_rmax() {
    float m = -3.4e38f;
    for (int i = blockIdx.x * 256 + threadIdx.x; i < NN; i += 256 * 256)
        m = fmaxf(m, g_logit[i]);
    m = wmax(m);
    __shared__ float sm[8];
    if ((threadIdx.x & 31) == 0) sm[threadIdx.x >> 5] = m;
    __syncthreads();
    if (threadIdx.x == 0) {
        float r = sm[0];
        for (int w = 1; w < 8; w++) r = fmaxf(r, sm[w]);
        g_red[blockIdx.x] = r;
    }
}
__global__ void k_rmax_fin() {
    float m = g_red[threadIdx.x];
    m = wmax(m);
    __shared__ float sm[8];
    if ((threadIdx.x & 31) == 0) sm[threadIdx.x >> 5] = m;
    __syncthreads();
    if (threadIdx.x == 0) {
        float r = sm[0];
        for (int w = 1; w < 8; w++) r = fmaxf(r, sm[w]);
        g_consts[0] = r;
    }
}
__global__ void k_rsum() {
    float mx = g_consts[0];
    float s = 0.f;
    for (int i = blockIdx.x * 256 + threadIdx.x; i < NN; i += 256 * 256)
        s += expf(g_logit[i] - mx);
    s = wsum(s);
    __shared__ float sm[8];
    if ((threadIdx.x & 31) == 0) sm[threadIdx.x >> 5] = s;
    __syncthreads();
    if (threadIdx.x == 0) {
        float r = 0.f;
        for (int w = 0; w < 8; w++) r += sm[w];
        g_red[256 + blockIdx.x] = r;
    }
}
__global__ void k_rsum_fin() {
    float s = g_red[256 + threadIdx.x];
    s = wsum(s);
    __shared__ float sm[8];
    if ((threadIdx.x & 31) == 0) sm[threadIdx.x >> 5] = s;
    __syncthreads();
    if (threadIdx.x == 0) {
        float r = 0.f;
        for (int w = 0; w < 8; w++) r += sm[w];
        g_consts[1] = 1.0f / r;
    }
}
__global__ void k_gate(float* __restrict__ out_gate) {
    int i = blockIdx.x * blockDim.x + threadIdx.x;
    if (i < NN) {
        float gv = expf(g_logit[i] - g_consts[0]) * g_consts[1];
        g_gate[i] = gv;
        if (out_gate) out_gate[i] = gv;
    }
}

// ---------------- batch boundaries + pooling ----------------
__global__ void k_bounds(const int* __restrict__ batch) {
    int t = threadIdx.x;
    if (t <= NB) {
        int lo = 0, hi = NN;
        while (lo < hi) {
            int mid = (lo + hi) >> 1;
            if (batch[mid] < t) lo = mid + 1; else hi = mid;
        }
        g_bstart[t] = lo;
    }
}
__global__ void k_pool() {
    int b = blockIdx.x / POOL_C;
    int c = blockIdx.x % POOL_C;
    int s = g_bstart[b], e = g_bstart[b + 1];
    long long len = e - s;
    int cs = s + (int)(len * c / POOL_C);
    int ce = s + (int)(len * (c + 1) / POOL_C);
    int d = threadIdx.x;
    float acc = 0.f;
    for (int n = cs; n < ce; n++) acc += g_gate[n] * g_h[(size_t)n * DD + d];
    g_pool_part[((size_t)b * POOL_C + c) * DD + d] = acc;
}
__global__ void k_pool_red() {
    int b = blockIdx.x, d = threadIdx.x;
    float s = 0.f;
    for (int c = 0; c < POOL_C; c++) s += g_pool_part[((size_t)b * POOL_C + c) * DD + d];
    g_pooled[b * DD + d] = s;
}

// ---------------- final out proj: gelu(ln(pooled @ out_w + out_b)) ----------------
__global__ void k_out(const float* __restrict__ W, const float* __restrict__ bias,
                      const float* __restrict__ lg, const float* __restrict__ lb,
                      float* __restrict__ outp) {
    __shared__ float sp[NB * DD];
    __shared__ float sz[NB * DD];
    int t = threadIdx.x;
#pragma unroll
    for (int j = 0; j < 4; j++) sp[t + 256 * j] = g_pooled[t + 256 * j];
    __syncthreads();
    int d = t & 127;
    int b0 = t >> 7;  // 0 or 1
    float acc[4];
#pragma unroll
    for (int j = 0; j < 4; j++) acc[j] = bias[d];
    for (int k = 0; k < DD; k++) {
        float wv = W[k * DD + d];
#pragma unroll
        for (int j = 0; j < 4; j++) acc[j] += sp[(b0 + 2 * j) * DD + k] * wv;
    }
#pragma unroll
    for (int j = 0; j < 4; j++) sz[(b0 + 2 * j) * DD + d] = acc[j];
    __syncthreads();
    int warp = t >> 5, lane = t & 31;  // 8 warps = 8 batch rows
    float4 v = *reinterpret_cast<float4*>(&sz[warp * DD + lane * 4]);
    float4 u = ln128(v, lg, lb, lane);
    outp[warp * DD + lane * 4 + 0] = geluf(u.x);
    outp[warp * DD + lane * 4 + 1] = geluf(u.y);
    outp[warp * DD + lane * 4 + 2] = geluf(u.z);
    outp[warp * DD + lane * 4 + 3] = geluf(u.w);
}

// ---------------- launch ----------------
extern "C" void kernel_launch(void* const* d_in, const int* in_sizes, int n_in,
                              void* d_out, int out_size) {
    const float* x        = (const float*)d_in[0];
    const int*   ei       = (const int*)d_in[1];
    const int*   batch    = (const int*)d_in[2];
    const float* w_in     = (const float*)d_in[3];
    const float* b_in     = (const float*)d_in[4];
    const float* ln_in_g  = (const float*)d_in[5];
    const float* ln_in_b  = (const float*)d_in[6];
    const float* gnn_w    = (const float*)d_in[7];
    const float* gnn_b    = (const float*)d_in[8];
    const float* gnn_ln_g = (const float*)d_in[9];
    const float* gnn_ln_b = (const float*)d_in[10];
    const float* norm_g   = (const float*)d_in[11];
    const float* norm_b   = (const float*)d_in[12];
    const float* gate_w1  = (const float*)d_in[13];
    const float* gate_b1  = (const float*)d_in[14];
    const float* gate_w2  = (const float*)d_in[15];
    const float* gate_b2  = (const float*)d_in[16];
    const float* out_w    = (const float*)d_in[17];
    const float* out_b    = (const float*)d_in[18];
    const float* out_ln_g = (const float*)d_in[19];
    const float* out_ln_b = (const float*)d_in[20];

    float* out = (float*)d_out;
    float* out_h    = (out_size >= NB * DD + NN * DD) ? out + NB * DD : nullptr;
    float* out_gate = (out_size >= NB * DD + NN * DD + NN) ? out + NB * DD + NN * DD : nullptr;

    float* p_h = nullptr;
    float* p_agg = nullptr;
    cudaGetSymbolAddress((void**)&p_h, g_h);
    cudaGetSymbolAddress((void**)&p_agg, g_agg);

    const int GT = (NN + 127) / 128;         // 391 GEMM tiles
    const int GW = (NN * 32 + 255) / 256;    // 6250 warp-per-node blocks
    const int GE = (NE + 255) / 256;         // 3125 edge blocks
    const int GN = (NN + 255) / 256;         // 196 node blocks

    // CSR build (per-call, deterministic result set)
    k_zero<<<GN, 256>>>();
    k_count<<<GE, 256>>>(ei);
    k_scan<<<1, 1024>>>();
    k_scatter<<<GE, 256>>>(ei);

    // input projection
    gemm_k<FIN, 0><<<GT, 256>>>(x, nullptr, w_in, b_in, NN);
    k_ln_gelu<<<GW, 256>>>(ln_in_g, ln_in_b);

    // GNN layers
    for (int i = 0; i < NL; i++) {
        k_aggregate<<<GW, 256>>>();
        gemm_k<256, 0><<<GT, 256>>>(p_h, p_agg, gnn_w + (size_t)i * 256 * 128,
                                    gnn_b + i * 128, NN);
        k_layer_post<<<GW, 256>>>(gnn_ln_g + i * 128, gnn_ln_b + i * 128,
                                  norm_g + i * 128, norm_b + i * 128,
                                  (i < NL - 1) ? 1 : 0,
                                  (i == NL - 1) ? out_h : nullptr);
    }

    // attention gate
    gemm_k<128, 1><<<GT, 256>>>(p_h, nullptr, gate_w1, gate_b1, NN);  // tanh epilogue
    k_logits<<<GW, 256>>>(gate_w2, gate_b2);
    k_rmax<<<256, 256>>>();
    k_rmax_fin<<<1, 256>>>();
    k_rsum<<<256, 256>>>();
    k_rsum_fin<<<1, 256>>>();
    k_gate<<<GN, 256>>>(out_gate);

    // pooling
    k_bounds<<<1, 32>>>(batch);
    k_pool<<<NB * POOL_C, 128>>>();
    k_pool_red<<<NB, 128>>>();

    // final projection
    k_out<<<1, 256>>>(out_w, out_b, out_ln_g, out_ln_b, out);
}

// round 3
// speedup vs baseline: 1.7138x; 1.7138x over previous
#include <cuda_runtime.h>
#include <cuda_bf16.h>
#include <math.h>
#include <stdint.h>

#define NN 50000
#define NE 800000
#define FIN 64
#define DD 128
#define NL 3
#define NB 8
#define POOL_C 64
#define NBLK 196          // ceil(NN/256)
#define WTOT 122880       // 128*64 + 3*128*256 + 128*128
#define SMEM_DYN 73728    // 4 * 128*72*2 bytes

// ---------------- scratch (device globals; no allocation) ----------------
__device__ __align__(16) float g_h[NN * DD];
__device__ __align__(16) __nv_bfloat16 g_ah[NN * 256];   // [node][0:128]=h, [128:256]=agg (hi)
__device__ __align__(16) __nv_bfloat16 g_al[NN * 256];   // lo residual
__device__ __align__(16) __nv_bfloat16 g_xh[NN * FIN];
__device__ __align__(16) __nv_bfloat16 g_xl[NN * FIN];
__device__ __align__(16) __nv_bfloat16 g_wh[WTOT];       // weights [n][k] per section
__device__ __align__(16) __nv_bfloat16 g_wl[WTOT];
__device__ int   g_cnt[NN];
__device__ int   g_inc[NBLK * 256];
__device__ int   g_blksum[256];
__device__ int   g_blkoff[256];
__device__ int   g_rowptr[NN + 1];
__device__ int   g_cursor[NN];
__device__ int   g_col[NE];
__device__ float g_deg[NN];
__device__ float g_logit[NN];
__device__ float g_gate[NN];
__device__ float g_red[512];
__device__ float g_consts[2];
__device__ int   g_bstart[NB + 1];
__device__ float g_pool_part[NB * POOL_C * DD];
__device__ float g_pooled[NB * DD];

// ---------------- helpers ----------------
__device__ __forceinline__ float geluf(float x) {
    return 0.5f * x * (1.0f + erff(x * 0.7071067811865476f));
}
__device__ __forceinline__ float wsum(float v) {
#pragma unroll
    for (int o = 16; o > 0; o >>= 1) v += __shfl_xor_sync(0xffffffffu, v, o);
    return v;
}
__device__ __forceinline__ float wmax(float v) {
#pragma unroll
    for (int o = 16; o > 0; o >>= 1) v = fmaxf(v, __shfl_xor_sync(0xffffffffu, v, o));
    return v;
}
__device__ __forceinline__ float qsum(float v) {
    v += __shfl_xor_sync(0xffffffffu, v, 1);
    v += __shfl_xor_sync(0xffffffffu, v, 2);
    return v;
}
__device__ __forceinline__ float4 ln128(float4 v, const float* __restrict__ g,
                                        const float* __restrict__ b, int lane) {
    float m = wsum(v.x + v.y + v.z + v.w) * (1.0f / 128.0f);
    float dx = v.x - m, dy = v.y - m, dz = v.z - m, dw = v.w - m;
    float var = wsum(dx * dx + dy * dy + dz * dz + dw * dw) * (1.0f / 128.0f);
    float rs = rsqrtf(var + 1e-5f);
    float4 gg = *reinterpret_cast<const float4*>(g + lane * 4);
    float4 bb = *reinterpret_cast<const float4*>(b + lane * 4);
    return make_float4(dx * rs * gg.x + bb.x, dy * rs * gg.y + bb.y,
                       dz * rs * gg.z + bb.z, dw * rs * gg.w + bb.w);
}
__device__ __forceinline__ uint32_t smem_u32(const void* p) {
    uint32_t a;
    asm("{ .reg .u64 t; cvta.to.shared.u64 t, %1; cvt.u32.u64 %0, t; }" : "=r"(a) : "l"(p));
    return a;
}
__device__ __forceinline__ void ldm4(uint32_t* r, uint32_t addr) {
    asm volatile("ldmatrix.sync.aligned.m8n8.x4.shared.b16 {%0,%1,%2,%3}, [%4];"
                 : "=r"(r[0]), "=r"(r[1]), "=r"(r[2]), "=r"(r[3]) : "r"(addr));
}
__device__ __forceinline__ void mma16816(float* d, const uint32_t* a, uint32_t b0, uint32_t b1) {
    asm volatile(
        "mma.sync.aligned.m16n8k16.row.col.f32.bf16.bf16.f32 "
        "{%0,%1,%2,%3}, {%4,%5,%6,%7}, {%8,%9}, {%0,%1,%2,%3};"
        : "+f"(d[0]), "+f"(d[1]), "+f"(d[2]), "+f"(d[3])
        : "r"(a[0]), "r"(a[1]), "r"(a[2]), "r"(a[3]), "r"(b0), "r"(b1));
}
__device__ __forceinline__ uint32_t pack_bf16x2(float a, float b) {
    __nv_bfloat162 t;
    t.x = __float2bfloat16(a);
    t.y = __float2bfloat16(b);
    return *reinterpret_cast<uint32_t*>(&t);
}

// ---------------- CSR build ----------------
__global__ void k_zero() {
    int i = blockIdx.x * blockDim.x + threadIdx.x;
    if (i < NN) g_cnt[i] = 0;
}
__global__ void k_count(const int* __restrict__ ei) {
    int e = blockIdx.x * blockDim.x + threadIdx.x;
    if (e < NE) atomicAdd(&g_cnt[ei[NE + e]], 1);
}
__global__ void k_scan1() {
    __shared__ int sw_[8];
    int b = blockIdx.x, t = threadIdx.x, i = b * 256 + t;
    int v = (i < NN) ? g_cnt[i] : 0;
    int x = v;
#pragma unroll
    for (int o = 1; o < 32; o <<= 1) {
        int y = __shfl_up_sync(0xffffffffu, x, o);
        if ((t & 31) >= o) x += y;
    }
    if ((t & 31) == 31) sw_[t >> 5] = x;
    __syncthreads();
    if (t == 0) {
        int s = 0;
        for (int w = 0; w < 8; w++) { int tmp = sw_[w]; sw_[w] = s; s += tmp; }
    }
    __syncthreads();
    int incl = x + sw_[t >> 5];
    g_inc[b * 256 + t] = incl;
    if (t == 255) g_blksum[b] = incl;
}
__global__ void k_scan2() {
    __shared__ int sw_[8];
    int t = threadIdx.x;
    int v = (t < NBLK) ? g_blksum[t] : 0;
    int x = v;
#pragma unroll
    for (int o = 1; o < 32; o <<= 1) {
        int y = __shfl_up_sync(0xffffffffu, x, o);
        if ((t & 31) >= o) x += y;
    }
    if ((t & 31) == 31) sw_[t >> 5] = x;
    __syncthreads();
    if (t == 0) {
        int s = 0;
        for (int w = 0; w < 8; w++) { int tmp = sw_[w]; sw_[w] = s; s += tmp; }
    }
    __syncthreads();
    g_blkoff[t] = x + sw_[t >> 5] - v;
}
__global__ void k_scan3() {
    int i = blockIdx.x * blockDim.x + threadIdx.x;
    if (i >= NN) return;
    int incl = g_inc[i] + g_blkoff[i >> 8];
    int v = g_cnt[i];
    g_rowptr[i + 1] = incl;
    g_cursor[i] = incl - v;
    g_deg[i] = (v > 0) ? (float)v : 1.0f;
    if (i == 0) g_rowptr[0] = 0;
}
__global__ void k_scatter(const int* __restrict__ ei) {
    int e = blockIdx.x * blockDim.x + threadIdx.x;
    if (e < NE) {
        int d = ei[NE + e];
        int p = atomicAdd(&g_cursor[d], 1);
        g_col[p] = ei[e];
    }
}

// ---------------- fp32 -> bf16 hi/lo splits ----------------
__global__ void k_split_w(const float* __restrict__ w_in, const float* __restrict__ gnn_w,
                          const float* __restrict__ gate_w1) {
    int i = blockIdx.x * blockDim.x + threadIdx.x;
    if (i >= WTOT) return;
    float v;
    if (i < 8192) {                       // w_in -> [n][k], n<128, k<64
        int n = i >> 6, k = i & 63;
        v = w_in[k * 128 + n];
    } else if (i < 106496) {              // gnn layer l -> [n][k], k<256
        int j = i - 8192;
        int l = j >> 15, r = j & 32767;
        int n = r >> 8, k = r & 255;
        v = gnn_w[((l << 8) + k) * 128 + n];
    } else {                              // gate_w1 -> [n][k], k<128
        int j = i - 106496;
        int n = j >> 7, k = j & 127;
        v = gate_w1[k * 128 + n];
    }
    __nv_bfloat16 hb = __float2bfloat16(v);
    g_wh[i] = hb;
    g_wl[i] = __float2bfloat16(v - __bfloat162float(hb));
}
__global__ void k_split_x(const float* __restrict__ x) {
    int i = blockIdx.x * blockDim.x + threadIdx.x;
    if (i >= NN * FIN) return;
    float v = x[i];
    __nv_bfloat16 hb = __float2bfloat16(v);
    g_xh[i] = hb;
    g_xl[i] = __float2bfloat16(v - __bfloat162float(hb));
}

// ---------------- HMMA GEMM (bf16 hi/lo, 3-pass) with fused epilogue ----------------
// D[128rows, 128] = A @ B^T, B[n][k] at g_wh/g_wl + boff.
// MODE 0: input proj (A=g_xh/g_xl stride 64): +bias -> LN -> GELU -> h + bf16 split
// MODE 1: GNN layer  (A=g_ah/g_al stride 256): +bias -> GELU -> LN -> LN [-> GELU+res] -> h + bf16
// MODE 2: gate       (A=g_ah/g_al stride 256): tanh(v+bias) . w2 -> logit
#define ASTRIDE 72
template <int KD, int MODE>
__global__ void __launch_bounds__(256)
gemm_mma(const float* __restrict__ bias, const float* __restrict__ p1,
         const float* __restrict__ p2, const float* __restrict__ p3,
         const float* __restrict__ p4, float* __restrict__ aux,
         int boff, int residual, int nrows) {
    extern __shared__ __align__(16) char dyn[];
    __nv_bfloat16* As_h = (__nv_bfloat16*)dyn;         // [128][72]
    __nv_bfloat16* As_l = As_h + 128 * ASTRIDE;
    __nv_bfloat16* Bs_h = As_l + 128 * ASTRIDE;
    __nv_bfloat16* Bs_l = Bs_h + 128 * ASTRIDE;
    __shared__ float s0[128], s1[128], s2[128], s3[128], s4[128];

    const int t = threadIdx.x;
    const int lane = t & 31, w = t >> 5;
    const int row0 = blockIdx.x * 128;

    if (t < 128) {
        s0[t] = bias[t];
        s1[t] = p1[t];
        if (MODE != 2) s2[t] = p2[t];
        if (MODE == 1) { s3[t] = p3[t]; s4[t] = p4[t]; }
    }

    const __nv_bfloat16* Ah = (MODE == 0) ? g_xh : g_ah;
    const __nv_bfloat16* Al = (MODE == 0) ? g_xl : g_al;
    const int strideA = (MODE == 0) ? 64 : 256;
    constexpr int NCH = KD / 64;

    float acc[16][4];
#pragma unroll
    for (int i = 0; i < 16; i++)
#pragma unroll
        for (int j = 0; j < 4; j++) acc[i][j] = 0.0f;

    const uint32_t sA_h = smem_u32(As_h), sA_l = smem_u32(As_l);
    const uint32_t sB_h = smem_u32(Bs_h), sB_l = smem_u32(Bs_l);
    // ldmatrix addresses (element offsets, *2 for bytes)
    const uint32_t a_off = ((w * 16 + (lane & 15)) * ASTRIDE + (lane >> 4) * 8) * 2;
    const int bg = lane >> 3;
    const uint32_t b_off = ((((bg & 2) ? 8 : 0) + (lane & 7)) * ASTRIDE + ((bg & 1) ? 8 : 0)) * 2;

    for (int c = 0; c < NCH; c++) {
#pragma unroll
        for (int q = 0; q < 4; q++) {
            int idx = q * 256 + t;       // 0..1023
            int r = idx >> 3, seg = idx & 7;
            const size_t aoff = (size_t)(row0 + r) * strideA + c * 64 + seg * 8;
            uint4 vh = make_uint4(0, 0, 0, 0), vl = make_uint4(0, 0, 0, 0);
            if (row0 + r < nrows) {
                vh = *(const uint4*)(Ah + aoff);
                vl = *(const uint4*)(Al + aoff);
            }
            *(uint4*)(As_h + r * ASTRIDE + seg * 8) = vh;
            *(uint4*)(As_l + r * ASTRIDE + seg * 8) = vl;
            const size_t boff2 = (size_t)boff + (size_t)r * KD + c * 64 + seg * 8;
            *(uint4*)(Bs_h + r * ASTRIDE + seg * 8) = *(const uint4*)(g_wh + boff2);
            *(uint4*)(Bs_l + r * ASTRIDE + seg * 8) = *(const uint4*)(g_wl + boff2);
        }
        __syncthreads();
#pragma unroll
        for (int kk = 0; kk < 64; kk += 16) {
            uint32_t aH[4], aL[4];
            ldm4(aH, sA_h + a_off + kk * 2);
            ldm4(aL, sA_l + a_off + kk * 2);
#pragma unroll
            for (int np = 0; np < 8; np++) {
                uint32_t bH[4], bL[4];
                uint32_t nb = (np * 16) * ASTRIDE * 2 + kk * 2;
                ldm4(bH, sB_h + b_off + nb);
                ldm4(bL, sB_l + b_off + nb);
                mma16816(acc[np * 2],     aH, bH[0], bH[1]);
                mma16816(acc[np * 2 + 1], aH, bH[2], bH[3]);
                mma16816(acc[np * 2],     aL, bH[0], bH[1]);
                mma16816(acc[np * 2 + 1], aL, bH[2], bH[3]);
                mma16816(acc[np * 2],     aH, bL[0], bL[1]);
                mma16816(acc[np * 2 + 1], aH, bL[2], bL[3]);
            }
        }
        __syncthreads();
    }

    // ---------------- fused epilogue ----------------
    const int qd = lane & 3;
#pragma unroll
    for (int ri = 0; ri < 2; ri++) {
        const int row = row0 + w * 16 + (lane >> 2) + ri * 8;
        const bool ok = row < nrows;

        if (MODE == 2) {
            float p = 0.f;
#pragma unroll
            for (int j = 0; j < 32; j++) {
                int n = (j >> 1) * 8 + qd * 2 + (j & 1);
                p += tanhf(acc[j >> 1][ri * 2 + (j & 1)] + s0[n]) * s1[n];
            }
            p = qsum(p);
            if (qd == 0 && ok) g_logit[row] = p + p3[0];
            continue;
        }

        float v[32];
        float sum = 0.f;
#pragma unroll
        for (int j = 0; j < 32; j++) {
            int n = (j >> 1) * 8 + qd * 2 + (j & 1);
            float u = acc[j >> 1][ri * 2 + (j & 1)] + s0[n];
            if (MODE == 1) u = geluf(u);
            v[j] = u;
            sum += u;
        }
        float m1 = qsum(sum) * (1.0f / 128.0f);
        float var = 0.f;
#pragma unroll
        for (int j = 0; j < 32; j++) { float d = v[j] - m1; var += d * d; }
        float rs = rsqrtf(qsum(var) * (1.0f / 128.0f) + 1e-5f);

        if (MODE == 0) {
            if (ok) {
                float2* hrow = (float2*)(g_h + (size_t)row * 128);
                uint32_t* ph = (uint32_t*)(g_ah + (size_t)row * 256);
                uint32_t* pl = (uint32_t*)(g_al + (size_t)row * 256);
#pragma unroll
                for (int k = 0; k < 16; k++) {
                    int n = k * 8 + qd * 2;
                    float o0 = geluf((v[2 * k] - m1) * rs * s1[n] + s2[n]);
                    float o1 = geluf((v[2 * k + 1] - m1) * rs * s1[n + 1] + s2[n + 1]);
                    hrow[n >> 1] = make_float2(o0, o1);
                    uint32_t hp = pack_bf16x2(o0, o1);
                    ph[n >> 1] = hp;
                    __nv_bfloat162 hh = *reinterpret_cast<__nv_bfloat162*>(&hp);
                    pl[n >> 1] = pack_bf16x2(o0 - __bfloat162float(hh.x),
                                             o1 - __bfloat162float(hh.y));
                }
            }
            continue;
        }

        // MODE 1: second LN
        float sum2 = 0.f;
#pragma unroll
        for (int j = 0; j < 32; j++) {
            int n = (j >> 1) * 8 + qd * 2 + (j & 1);
            float u = (v[j] - m1) * rs * s1[n] + s2[n];
            v[j] = u;
            sum2 += u;
        }
        float m2 = qsum(sum2) * (1.0f / 128.0f);
        float var2 = 0.f;
#pragma unroll
        for (int j = 0; j < 32; j++) { float d = v[j] - m2; var2 += d * d; }
        float rs2 = rsqrtf(qsum(var2) * (1.0f / 128.0f) + 1e-5f);

        if (ok) {
            float2* hrow = (float2*)(g_h + (size_t)row * 128);
            float2* arow = aux ? (float2*)(aux + (size_t)row * 128) : nullptr;
            uint32_t* ph = (uint32_t*)(g_ah + (size_t)row * 256);
            uint32_t* pl = (uint32_t*)(g_al + (size_t)row * 256);
#pragma unroll
            for (int k = 0; k < 16; k++) {
                int n = k * 8 + qd * 2;
                float o0 = (v[2 * k] - m2) * rs2 * s3[n] + s4[n];
                float o1 = (v[2 * k + 1] - m2) * rs2 * s3[n + 1] + s4[n + 1];
                if (residual) {
                    float2 ho = hrow[n >> 1];
                    o0 = geluf(o0) + ho.x;
                    o1 = geluf(o1) + ho.y;
                }
                hrow[n >> 1] = make_float2(o0, o1);
                if (arow) arow[n >> 1] = make_float2(o0, o1);
                uint32_t hp = pack_bf16x2(o0, o1);
                ph[n >> 1] = hp;
                __nv_bfloat162 hh = *reinterpret_cast<__nv_bfloat162*>(&hp);
                pl[n >> 1] = pack_bf16x2(o0 - __bfloat162float(hh.x),
                                         o1 - __bfloat162float(hh.y));
            }
        }
    }
}

// ---------------- aggregation: mean over CSR neighbors -> bf16 hi/lo ----------------
__global__ void k_aggregate() {
    int gid = blockIdx.x * blockDim.x + threadIdx.x;
    int node = gid >> 5, lane = gid & 31;
    if (node >= NN) return;
    int s = g_rowptr[node], e = g_rowptr[node + 1];
    float4 acc = make_float4(0.f, 0.f, 0.f, 0.f);
    const float4* h4 = reinterpret_cast<const float4*>(g_h);
    for (int i = s; i < e; i++) {
        int src = g_col[i];
        float4 v = h4[(size_t)src * 32 + lane];
        acc.x += v.x; acc.y += v.y; acc.z += v.z; acc.w += v.w;
    }
    float inv = 1.0f / g_deg[node];
    acc.x *= inv; acc.y *= inv; acc.z *= inv; acc.w *= inv;
    size_t base = (size_t)node * 256 + 128 + lane * 4;
    uint32_t h0 = pack_bf16x2(acc.x, acc.y);
    uint32_t h1 = pack_bf16x2(acc.z, acc.w);
    ((uint32_t*)(g_ah + base))[0] = h0;
    ((uint32_t*)(g_ah + base))[1] = h1;
    __nv_bfloat162 a0 = *reinterpret_cast<__nv_bfloat162*>(&h0);
    __nv_bfloat162 a1 = *reinterpret_cast<__nv_bfloat162*>(&h1);
    ((uint32_t*)(g_al + base))[0] = pack_bf16x2(acc.x - __bfloat162float(a0.x),
                                                acc.y - __bfloat162float(a0.y));
    ((uint32_t*)(g_al + base))[1] = pack_bf16x2(acc.z - __bfloat162float(a1.x),
                                                acc.w - __bfloat162float(a1.y));
}

// ---------------- softmax ----------------
__global__ void k_rmax() {
    float m = -3.4e38f;
    for (int i = blockIdx.x * 256 + threadIdx.x; i < NN; i += 256 * 256)
        m = fmaxf(m, g_logit[i]);
    m = wmax(m);
    __shared__ float sm[8];
    if ((threadIdx.x & 31) == 0) sm[threadIdx.x >> 5] = m;
    __syncthreads();
    if (threadIdx.x == 0) {
        float r = sm[0];
        for (int w = 1; w < 8; w++) r = fmaxf(r, sm[w]);
        g_red[blockIdx.x] = r;
    }
}
__global__ void k_rmax_fin() {
    float m = g_red[threadIdx.x];
    m = wmax(m);
    __shared__ float sm[8];
    if ((threadIdx.x & 31) == 0) sm[threadIdx.x >> 5] = m;
    __syncthreads();
    if (threadIdx.x == 0) {
        float r = sm[0];
        for (int w = 1; w < 8; w++) r = fmaxf(r, sm[w]);
        g_consts[0] = r;
    }
}
__global__ void k_rsum() {
    float mx = g_consts[0];
    float s = 0.f;
    for (int i = blockIdx.x * 256 + threadIdx.x; i < NN; i += 256 * 256)
        s += expf(g_logit[i] - mx);
    s = wsum(s);
    __shared__ float sm[8];
    if ((threadIdx.x & 31) == 0) sm[threadIdx.x >> 5] = s;
    __syncthreads();
    if (threadIdx.x == 0) {
        float r = 0.f;
        for (int w = 0; w < 8; w++) r += sm[w];
        g_red[256 + blockIdx.x] = r;
    }
}
__global__ void k_rsum_fin() {
    float s = g_red[256 + threadIdx.x];
    s = wsum(s);
    __shared__ float sm[8];
    if ((threadIdx.x & 31) == 0) sm[threadIdx.x >> 5] = s;
    __syncthreads();
    if (threadIdx.x == 0) {
        float r = 0.f;
        for (int w = 0; w < 8; w++) r += sm[w];
        g_consts[1] = 1.0f / r;
    }
}
__global__ void k_gate(float* __restrict__ out_gate) {
    int i = blockIdx.x * blockDim.x + threadIdx.x;
    if (i < NN) {
        float gv = expf(g_logit[i] - g_consts[0]) * g_consts[1];
        g_gate[i] = gv;
        if (out_gate) out_gate[i] = gv;
    }
}

// ---------------- batch boundaries + pooling ----------------
__global__ void k_bounds(const int* __restrict__ batch) {
    int t = threadIdx.x;
    if (t <= NB) {
        int lo = 0, hi = NN;
        while (lo < hi) {
            int mid = (lo + hi) >> 1;
            if (batch[mid] < t) lo = mid + 1; else hi = mid;
        }
        g_bstart[t] = lo;
    }
}
__global__ void k_pool() {
    int b = blockIdx.x / POOL_C;
    int c = blockIdx.x % POOL_C;
    int s = g_bstart[b], e = g_bstart[b + 1];
    long long len = e - s;
    int cs = s + (int)(len * c / POOL_C);
    int ce = s + (int)(len * (c + 1) / POOL_C);
    int d = threadIdx.x;
    float acc = 0.f;
    for (int n = cs; n < ce; n++) acc += g_gate[n] * g_h[(size_t)n * DD + d];
    g_pool_part[((size_t)b * POOL_C + c) * DD + d] = acc;
}
__global__ void k_pool_red() {
    int b = blockIdx.x, d = threadIdx.x;
    float s = 0.f;
    for (int c = 0; c < POOL_C; c++) s += g_pool_part[((size_t)b * POOL_C + c) * DD + d];
    g_pooled[b * DD + d] = s;
}

// ---------------- final out proj ----------------
__global__ void k_out(const float* __restrict__ W, const float* __restrict__ bias,
                      const float* __restrict__ lg, const float* __restrict__ lb,
                      float* __restrict__ outp) {
    __shared__ float sp[NB * DD];
    __shared__ float sz[NB * DD];
    int t = threadIdx.x;
#pragma unroll
    for (int j = 0; j < 4; j++) sp[t + 256 * j] = g_pooled[t + 256 * j];
    __syncthreads();
    int d = t & 127;
    int b0 = t >> 7;
    float acc[4];
#pragma unroll
    for (int j = 0; j < 4; j++) acc[j] = bias[d];
    for (int k = 0; k < DD; k++) {
        float wv = W[k * DD + d];
#pragma unroll
        for (int j = 0; j < 4; j++) acc[j] += sp[(b0 + 2 * j) * DD + k] * wv;
    }
#pragma unroll
    for (int j = 0; j < 4; j++) sz[(b0 + 2 * j) * DD + d] = acc[j];
    __syncthreads();
    int warp = t >> 5, lane = t & 31;
    float4 v = *reinterpret_cast<float4*>(&sz[warp * DD + lane * 4]);
    float4 u = ln128(v, lg, lb, lane);
    outp[warp * DD + lane * 4 + 0] = geluf(u.x);
    outp[warp * DD + lane * 4 + 1] = geluf(u.y);
    outp[warp * DD + lane * 4 + 2] = geluf(u.z);
    outp[warp * DD + lane * 4 + 3] = geluf(u.w);
}

// ---------------- launch ----------------
extern "C" void kernel_launch(void* const* d_in, const int* in_sizes, int n_in,
                              void* d_out, int out_size) {
    const float* x        = (const float*)d_in[0];
    const int*   ei       = (const int*)d_in[1];
    const int*   batch    = (const int*)d_in[2];
    const float* w_in     = (const float*)d_in[3];
    const float* b_in     = (const float*)d_in[4];
    const float* ln_in_g  = (const float*)d_in[5];
    const float* ln_in_b  = (const float*)d_in[6];
    const float* gnn_w    = (const float*)d_in[7];
    const float* gnn_b    = (const float*)d_in[8];
    const float* gnn_ln_g = (const float*)d_in[9];
    const float* gnn_ln_b = (const float*)d_in[10];
    const float* norm_g   = (const float*)d_in[11];
    const float* norm_b   = (const float*)d_in[12];
    const float* gate_w1  = (const float*)d_in[13];
    const float* gate_b1  = (const float*)d_in[14];
    const float* gate_w2  = (const float*)d_in[15];
    const float* gate_b2  = (const float*)d_in[16];
    const float* out_w    = (const float*)d_in[17];
    const float* out_b    = (const float*)d_in[18];
    const float* out_ln_g = (const float*)d_in[19];
    const float* out_ln_b = (const float*)d_in[20];

    float* out = (float*)d_out;
    float* out_h    = (out_size >= NB * DD + NN * DD) ? out + NB * DD : nullptr;
    float* out_gate = (out_size >= NB * DD + NN * DD + NN) ? out + NB * DD + NN * DD : nullptr;

    cudaFuncSetAttribute((const void*)gemm_mma<64, 0>,
                         cudaFuncAttributeMaxDynamicSharedMemorySize, SMEM_DYN);
    cudaFuncSetAttribute((const void*)gemm_mma<256, 1>,
                         cudaFuncAttributeMaxDynamicSharedMemorySize, SMEM_DYN);
    cudaFuncSetAttribute((const void*)gemm_mma<128, 2>,
                         cudaFuncAttributeMaxDynamicSharedMemorySize, SMEM_DYN);

    const int GT = (NN + 127) / 128;
    const int GW = (NN * 32 + 255) / 256;
    const int GE = (NE + 255) / 256;
    const int GN = (NN + 255) / 256;

    // CSR build
    k_zero<<<GN, 256>>>();
    k_count<<<GE, 256>>>(ei);
    k_scan1<<<NBLK, 256>>>();
    k_scan2<<<1, 256>>>();
    k_scan3<<<GN, 256>>>();
    k_scatter<<<GE, 256>>>(ei);

    // bf16 hi/lo splits
    k_split_w<<<(WTOT + 255) / 256, 256>>>(w_in, gnn_w, gate_w1);
    k_split_x<<<(NN * FIN + 255) / 256, 256>>>(x);

    // input projection (+ fused LN->GELU)
    gemm_mma<64, 0><<<GT, 256, SMEM_DYN>>>(b_in, ln_in_g, ln_in_b, nullptr, nullptr,
                                           nullptr, 0, 0, NN);

    // GNN layers (+ fused GELU->LN->LN[->GELU+res])
    for (int l = 0; l < NL; l++) {
        k_aggregate<<<GW, 256>>>();
        gemm_mma<256, 1><<<GT, 256, SMEM_DYN>>>(gnn_b + l * 128,
                                                gnn_ln_g + l * 128, gnn_ln_b + l * 128,
                                                norm_g + l * 128, norm_b + l * 128,
                                                (l == NL - 1) ? out_h : nullptr,
                                                8192 + l * 32768,
                                                (l < NL - 1) ? 1 : 0, NN);
    }

    // gate (+ fused tanh + dot(w2))
    gemm_mma<128, 2><<<GT, 256, SMEM_DYN>>>(gate_b1, gate_w2, nullptr, gate_b2, nullptr,
                                            nullptr, 106496, 0, NN);

    // softmax over all nodes
    k_rmax<<<256, 256>>>();
    k_rmax_fin<<<1, 256>>>();
    k_rsum<<<256, 256>>>();
    k_rsum_fin<<<1, 256>>>();
    k_gate<<<GN, 256>>>(out_gate);

    // pooling
    k_bounds<<<1, 32>>>(batch);
    k_pool<<<NB * POOL_C, 128>>>();
    k_pool_red<<<NB, 128>>>();

    // final projection
    k_out<<<1, 256>>>(out_w, out_b, out_ln_g, out_ln_b, out);
}

// round 4
// speedup vs baseline: 1.9226x; 1.1218x over previous
#include <cuda_runtime.h>
#include <cuda_bf16.h>
#include <cuda_fp16.h>
#include <math.h>
#include <stdint.h>

#define NN 50000
#define NE 800000
#define FIN 64
#define DD 128
#define NL 3
#define NB 8
#define POOL_C 64
#define NBLK 196          // ceil(NN/256)
#define WTOT 122880       // 128*64 + 3*128*256 + 128*128
#define SMEM_DYN 73728    // 4 * 128*72*2 bytes

// ---------------- scratch (device globals; no allocation) ----------------
__device__ __align__(16) float g_h[NN * DD];        // fp32 hidden
__device__ __align__(16) __half g_hh[NN * DD];      // fp16 copy for gathers
__device__ __align__(16) float g_agg[NN * DD];      // fp32 aggregate
__device__ __align__(16) __nv_bfloat16 g_wh[WTOT];  // weights [n][k], bf16 hi
__device__ __align__(16) __nv_bfloat16 g_wl[WTOT];  // bf16 lo
__device__ int   g_cnt[NN];
__device__ int   g_inc[NBLK * 256];
__device__ int   g_blksum[NBLK];
__device__ int   g_rowptr[NN + 1];
__device__ int   g_cursor[NN];
__device__ int   g_col[NE];
__device__ float g_deg[NN];
__device__ float g_logit[NN];
__device__ float g_red[256];
__device__ float g_consts[2];
__device__ int   g_bstart[NB + 1];
__device__ float g_pool_part[NB * POOL_C * DD];
__device__ float g_pooled[NB * DD];

// ---------------- helpers ----------------
__device__ __forceinline__ float geluf(float x) {
    return 0.5f * x * (1.0f + erff(x * 0.7071067811865476f));
}
__device__ __forceinline__ float wsum(float v) {
#pragma unroll
    for (int o = 16; o > 0; o >>= 1) v += __shfl_xor_sync(0xffffffffu, v, o);
    return v;
}
__device__ __forceinline__ int wsumi(int v) {
#pragma unroll
    for (int o = 16; o > 0; o >>= 1) v += __shfl_xor_sync(0xffffffffu, v, o);
    return v;
}
__device__ __forceinline__ float qsum(float v) {
    v += __shfl_xor_sync(0xffffffffu, v, 1);
    v += __shfl_xor_sync(0xffffffffu, v, 2);
    return v;
}
__device__ __forceinline__ float4 ln128(float4 v, const float* __restrict__ g,
                                        const float* __restrict__ b, int lane) {
    float m = wsum(v.x + v.y + v.z + v.w) * (1.0f / 128.0f);
    float dx = v.x - m, dy = v.y - m, dz = v.z - m, dw = v.w - m;
    float var = wsum(dx * dx + dy * dy + dz * dz + dw * dw) * (1.0f / 128.0f);
    float rs = rsqrtf(var + 1e-5f);
    float4 gg = *reinterpret_cast<const float4*>(g + lane * 4);
    float4 bb = *reinterpret_cast<const float4*>(b + lane * 4);
    return make_float4(dx * rs * gg.x + bb.x, dy * rs * gg.y + bb.y,
                       dz * rs * gg.z + bb.z, dw * rs * gg.w + bb.w);
}
__device__ __forceinline__ uint32_t smem_u32(const void* p) {
    uint32_t a;
    asm("{ .reg .u64 t; cvta.to.shared.u64 t, %1; cvt.u32.u64 %0, t; }" : "=r"(a) : "l"(p));
    return a;
}
__device__ __forceinline__ void ldm4(uint32_t* r, uint32_t addr) {
    asm volatile("ldmatrix.sync.aligned.m8n8.x4.shared.b16 {%0,%1,%2,%3}, [%4];"
                 : "=r"(r[0]), "=r"(r[1]), "=r"(r[2]), "=r"(r[3]) : "r"(addr));
}
__device__ __forceinline__ void mma16816(float* d, const uint32_t* a, uint32_t b0, uint32_t b1) {
    asm volatile(
        "mma.sync.aligned.m16n8k16.row.col.f32.bf16.bf16.f32 "
        "{%0,%1,%2,%3}, {%4,%5,%6,%7}, {%8,%9}, {%0,%1,%2,%3};"
        : "+f"(d[0]), "+f"(d[1]), "+f"(d[2]), "+f"(d[3])
        : "r"(a[0]), "r"(a[1]), "r"(a[2]), "r"(a[3]), "r"(b0), "r"(b1));
}
__device__ __forceinline__ uint32_t pack_hi2(float a, float b) {
    __nv_bfloat162 t;
    t.x = __float2bfloat16(a);
    t.y = __float2bfloat16(b);
    return *reinterpret_cast<uint32_t*>(&t);
}
__device__ __forceinline__ void split2(float a, float b, uint32_t& hi, uint32_t& lo) {
    __nv_bfloat16 ha = __float2bfloat16(a), hb = __float2bfloat16(b);
    __nv_bfloat162 th; th.x = ha; th.y = hb;
    hi = *reinterpret_cast<uint32_t*>(&th);
    __nv_bfloat162 tl;
    tl.x = __float2bfloat16(a - __bfloat162float(ha));
    tl.y = __float2bfloat16(b - __bfloat162float(hb));
    lo = *reinterpret_cast<uint32_t*>(&tl);
}

// ---------------- CSR build ----------------
__global__ void k_zero() {
    int i = blockIdx.x * blockDim.x + threadIdx.x;
    if (i < NN) g_cnt[i] = 0;
}
__global__ void k_count(const int* __restrict__ ei) {
    int e = blockIdx.x * blockDim.x + threadIdx.x;
    if (e < NE) atomicAdd(&g_cnt[ei[NE + e]], 1);
}
__global__ void k_scan1() {
    __shared__ int sw_[8];
    int b = blockIdx.x, t = threadIdx.x, i = b * 256 + t;
    int v = (i < NN) ? g_cnt[i] : 0;
    int x = v;
#pragma unroll
    for (int o = 1; o < 32; o <<= 1) {
        int y = __shfl_up_sync(0xffffffffu, x, o);
        if ((t & 31) >= o) x += y;
    }
    if ((t & 31) == 31) sw_[t >> 5] = x;
    __syncthreads();
    if (t == 0) {
        int s = 0;
        for (int w = 0; w < 8; w++) { int tmp = sw_[w]; sw_[w] = s; s += tmp; }
    }
    __syncthreads();
    int incl = x + sw_[t >> 5];
    g_inc[b * 256 + t] = incl;
    if (t == 255) g_blksum[b] = incl;
}
// merged scan2+scan3: each block reduces its prefix over g_blksum
__global__ void k_scan3() {
    __shared__ int soff;
    int blk = blockIdx.x, t = threadIdx.x;
    if (t < 32) {
        int s = 0;
        for (int b = t; b < blk; b += 32) s += g_blksum[b];
        s = wsumi(s);
        if (t == 0) soff = s;
    }
    __syncthreads();
    int i = blk * 256 + t;
    if (i >= NN) return;
    int incl = g_inc[i] + soff;
    int v = g_cnt[i];
    g_rowptr[i + 1] = incl;
    g_cursor[i] = incl - v;
    g_deg[i] = (v > 0) ? (float)v : 1.0f;
    if (i == 0) g_rowptr[0] = 0;
}
__global__ void k_scatter(const int* __restrict__ ei) {
    int e = blockIdx.x * blockDim.x + threadIdx.x;
    if (e < NE) {
        int d = ei[NE + e];
        int p = atomicAdd(&g_cursor[d], 1);
        g_col[p] = ei[e];
    }
}

// ---------------- weight split (fp32 -> bf16 hi/lo, transposed to [n][k]) ----------------
__global__ void k_split_w(const float* __restrict__ w_in, const float* __restrict__ gnn_w,
                          const float* __restrict__ gate_w1) {
    int i = blockIdx.x * blockDim.x + threadIdx.x;
    if (i >= WTOT) return;
    float v;
    if (i < 8192) {
        int n = i >> 6, k = i & 63;
        v = w_in[k * 128 + n];
    } else if (i < 106496) {
        int j = i - 8192;
        int l = j >> 15, r = j & 32767;
        int n = r >> 8, k = r & 255;
        v = gnn_w[((l << 8) + k) * 128 + n];
    } else {
        int j = i - 106496;
        int n = j >> 7, k = j & 127;
        v = gate_w1[k * 128 + n];
    }
    __nv_bfloat16 hb = __float2bfloat16(v);
    g_wh[i] = hb;
    g_wl[i] = __float2bfloat16(v - __bfloat162float(hb));
}

// ---------------- HMMA GEMM (bf16 hi/lo 3-pass) with on-the-fly A split + fused epilogue ----------------
// MODE 0: input proj (A = xin fp32, stride 64):  +bias -> LN -> GELU -> g_h + g_hh
// MODE 1: GNN layer  (A = [g_h | g_agg] fp32):   +bias -> GELU -> LN -> LN [-> GELU+res] -> g_h + g_hh
// MODE 2: gate       (A = g_h fp32):             tanh(v+bias) . w2 -> logit
#define ASTRIDE 72
template <int KD, int MODE>
__global__ void __launch_bounds__(256)
gemm_mma(const float* __restrict__ xin,
         const float* __restrict__ bias, const float* __restrict__ p1,
         const float* __restrict__ p2, const float* __restrict__ p3,
         const float* __restrict__ p4, float* __restrict__ aux,
         int boff, int residual, int nrows) {
    extern __shared__ __align__(16) char dyn[];
    __nv_bfloat16* As_h = (__nv_bfloat16*)dyn;         // [128][72]
    __nv_bfloat16* As_l = As_h + 128 * ASTRIDE;
    __nv_bfloat16* Bs_h = As_l + 128 * ASTRIDE;
    __nv_bfloat16* Bs_l = Bs_h + 128 * ASTRIDE;
    __shared__ float s0[128], s1[128], s2[128], s3[128], s4[128];

    const int t = threadIdx.x;
    const int lane = t & 31, w = t >> 5;
    const int row0 = blockIdx.x * 128;

    if (t < 128) {
        s0[t] = bias[t];
        s1[t] = p1[t];
        if (MODE != 2) s2[t] = p2[t];
        if (MODE == 1) { s3[t] = p3[t]; s4[t] = p4[t]; }
    }

    constexpr int NCH = KD / 64;

    float acc[16][4];
#pragma unroll
    for (int i = 0; i < 16; i++)
#pragma unroll
        for (int j = 0; j < 4; j++) acc[i][j] = 0.0f;

    const uint32_t sA_h = smem_u32(As_h), sA_l = smem_u32(As_l);
    const uint32_t sB_h = smem_u32(Bs_h), sB_l = smem_u32(Bs_l);
    const uint32_t a_off = ((w * 16 + (lane & 15)) * ASTRIDE + (lane >> 4) * 8) * 2;
    const int bg = lane >> 3;
    const uint32_t b_off = ((((bg & 2) ? 8 : 0) + (lane & 7)) * ASTRIDE + ((bg & 1) ? 8 : 0)) * 2;

#pragma unroll
    for (int c = 0; c < NCH; c++) {
#pragma unroll
        for (int q = 0; q < 4; q++) {
            int idx = q * 256 + t;       // 0..1023
            int r = idx >> 3, seg = idx & 7;
            const float* src;
            if (MODE == 0)
                src = xin + (size_t)(row0 + r) * 64 + seg * 8;
            else if (MODE == 2)
                src = g_h + (size_t)(row0 + r) * 128 + c * 64 + seg * 8;
            else
                src = (c < 2)
                    ? g_h + (size_t)(row0 + r) * 128 + c * 64 + seg * 8
                    : g_agg + (size_t)(row0 + r) * 128 + (c - 2) * 64 + seg * 8;
            float4 f0 = make_float4(0.f, 0.f, 0.f, 0.f);
            float4 f1 = make_float4(0.f, 0.f, 0.f, 0.f);
            if (row0 + r < nrows) {
                f0 = *(const float4*)src;
                f1 = *(const float4*)(src + 4);
            }
            uint4 vh, vl;
            split2(f0.x, f0.y, vh.x, vl.x);
            split2(f0.z, f0.w, vh.y, vl.y);
            split2(f1.x, f1.y, vh.z, vl.z);
            split2(f1.z, f1.w, vh.w, vl.w);
            *(uint4*)(As_h + r * ASTRIDE + seg * 8) = vh;
            *(uint4*)(As_l + r * ASTRIDE + seg * 8) = vl;
            const size_t boff2 = (size_t)boff + (size_t)r * KD + c * 64 + seg * 8;
            *(uint4*)(Bs_h + r * ASTRIDE + seg * 8) = *(const uint4*)(g_wh + boff2);
            *(uint4*)(Bs_l + r * ASTRIDE + seg * 8) = *(const uint4*)(g_wl + boff2);
        }
        __syncthreads();
#pragma unroll
        for (int kk = 0; kk < 64; kk += 16) {
            uint32_t aH[4], aL[4];
            ldm4(aH, sA_h + a_off + kk * 2);
            ldm4(aL, sA_l + a_off + kk * 2);
#pragma unroll
            for (int np = 0; np < 8; np++) {
                uint32_t bH[4], bL[4];
                uint32_t nb = (np * 16) * ASTRIDE * 2 + kk * 2;
                ldm4(bH, sB_h + b_off + nb);
                ldm4(bL, sB_l + b_off + nb);
                mma16816(acc[np * 2],     aH, bH[0], bH[1]);
                mma16816(acc[np * 2 + 1], aH, bH[2], bH[3]);
                mma16816(acc[np * 2],     aL, bH[0], bH[1]);
                mma16816(acc[np * 2 + 1], aL, bH[2], bH[3]);
                mma16816(acc[np * 2],     aH, bL[0], bL[1]);
                mma16816(acc[np * 2 + 1], aH, bL[2], bL[3]);
            }
        }
        __syncthreads();
    }

    // ---------------- fused epilogue ----------------
    const int qd = lane & 3;
#pragma unroll
    for (int ri = 0; ri < 2; ri++) {
        const int row = row0 + w * 16 + (lane >> 2) + ri * 8;
        const bool ok = row < nrows;

        if (MODE == 2) {
            float p = 0.f;
#pragma unroll
            for (int j = 0; j < 32; j++) {
                int n = (j >> 1) * 8 + qd * 2 + (j & 1);
                p += tanhf(acc[j >> 1][ri * 2 + (j & 1)] + s0[n]) * s1[n];
            }
            p = qsum(p);
            if (qd == 0 && ok) g_logit[row] = p + p3[0];
            continue;
        }

        float v[32];
        float sum = 0.f;
#pragma unroll
        for (int j = 0; j < 32; j++) {
            int n = (j >> 1) * 8 + qd * 2 + (j & 1);
            float u = acc[j >> 1][ri * 2 + (j & 1)] + s0[n];
            if (MODE == 1) u = geluf(u);
            v[j] = u;
            sum += u;
        }
        float m1 = qsum(sum) * (1.0f / 128.0f);
        float var = 0.f;
#pragma unroll
        for (int j = 0; j < 32; j++) { float d = v[j] - m1; var += d * d; }
        float rs = rsqrtf(qsum(var) * (1.0f / 128.0f) + 1e-5f);

        if (MODE == 0) {
            if (ok) {
                float2* hrow = (float2*)(g_h + (size_t)row * 128);
                uint32_t* phh = (uint32_t*)(g_hh + (size_t)row * 128);
#pragma unroll
                for (int k = 0; k < 16; k++) {
                    int n = k * 8 + qd * 2;
                    float o0 = geluf((v[2 * k] - m1) * rs * s1[n] + s2[n]);
                    float o1 = geluf((v[2 * k + 1] - m1) * rs * s1[n + 1] + s2[n + 1]);
                    hrow[n >> 1] = make_float2(o0, o1);
                    __half2 hp = __floats2half2_rn(o0, o1);
                    phh[n >> 1] = *reinterpret_cast<uint32_t*>(&hp);
                }
            }
            continue;
        }

        // MODE 1: second LN
        float sum2 = 0.f;
#pragma unroll
        for (int j = 0; j < 32; j++) {
            int n = (j >> 1) * 8 + qd * 2 + (j & 1);
            float u = (v[j] - m1) * rs * s1[n] + s2[n];
            v[j] = u;
            sum2 += u;
        }
        float m2 = qsum(sum2) * (1.0f / 128.0f);
        float var2 = 0.f;
#pragma unroll
        for (int j = 0; j < 32; j++) { float d = v[j] - m2; var2 += d * d; }
        float rs2 = rsqrtf(qsum(var2) * (1.0f / 128.0f) + 1e-5f);

        if (ok) {
            float2* hrow = (float2*)(g_h + (size_t)row * 128);
            float2* arow = aux ? (float2*)(aux + (size_t)row * 128) : nullptr;
            uint32_t* phh = (uint32_t*)(g_hh + (size_t)row * 128);
#pragma unroll
            for (int k = 0; k < 16; k++) {
                int n = k * 8 + qd * 2;
                float o0 = (v[2 * k] - m2) * rs2 * s3[n] + s4[n];
                float o1 = (v[2 * k + 1] - m2) * rs2 * s3[n + 1] + s4[n + 1];
                if (residual) {
                    float2 ho = hrow[n >> 1];
                    o0 = geluf(o0) + ho.x;
                    o1 = geluf(o1) + ho.y;
                }
                hrow[n >> 1] = make_float2(o0, o1);
                if (arow) arow[n >> 1] = make_float2(o0, o1);
                __half2 hp = __floats2half2_rn(o0, o1);
                phh[n >> 1] = *reinterpret_cast<uint32_t*>(&hp);
            }
        }
    }
}

// ---------------- aggregation: mean over CSR neighbors (fp16 gather) -> fp32 g_agg ----------------
__global__ void k_aggregate() {
    int gid = blockIdx.x * blockDim.x + threadIdx.x;
    int node = gid >> 5, lane = gid & 31;
    if (node >= NN) return;
    int s = g_rowptr[node], e = g_rowptr[node + 1];
    float4 acc = make_float4(0.f, 0.f, 0.f, 0.f);
    const uint2* hh = reinterpret_cast<const uint2*>(g_hh);
    for (int i = s; i < e; i++) {
        int src = g_col[i];
        uint2 v = hh[(size_t)src * 32 + lane];
        float2 f0 = __half22float2(*reinterpret_cast<__half2*>(&v.x));
        float2 f1 = __half22float2(*reinterpret_cast<__half2*>(&v.y));
        acc.x += f0.x; acc.y += f0.y; acc.z += f1.x; acc.w += f1.y;
    }
    float inv = 1.0f / g_deg[node];
    acc.x *= inv; acc.y *= inv; acc.z *= inv; acc.w *= inv;
    *reinterpret_cast<float4*>(g_agg + (size_t)node * 128 + lane * 4) = acc;
}

// ---------------- softmax sum (no max needed: logits bounded) ----------------
__global__ void k_rsum() {
    float s = 0.f;
    for (int i = blockIdx.x * 256 + threadIdx.x; i < NN; i += 256 * 256)
        s += expf(g_logit[i]);
    s = wsum(s);
    __shared__ float sm[8];
    if ((threadIdx.x & 31) == 0) sm[threadIdx.x >> 5] = s;
    __syncthreads();
    if (threadIdx.x == 0) {
        float r = 0.f;
        for (int w = 0; w < 8; w++) r += sm[w];
        g_red[blockIdx.x] = r;
    }
}
__global__ void k_rsum_fin(const int* __restrict__ batch) {
    int t = threadIdx.x;
    float s = g_red[t];
    s = wsum(s);
    __shared__ float sm[8];
    if ((t & 31) == 0) sm[t >> 5] = s;
    __syncthreads();
    if (t == 0) {
        float r = 0.f;
        for (int w = 0; w < 8; w++) r += sm[w];
        g_consts[1] = 1.0f / r;
    }
    // batch boundaries (folded)
    if (t <= NB) {
        int lo = 0, hi = NN;
        while (lo < hi) {
            int mid = (lo + hi) >> 1;
            if (batch[mid] < t) lo = mid + 1; else hi = mid;
        }
        g_bstart[t] = lo;
    }
}

// ---------------- pooling (gate computed inline) ----------------
__global__ void k_pool(float* __restrict__ out_gate) {
    int b = blockIdx.x / POOL_C;
    int c = blockIdx.x % POOL_C;
    int s = g_bstart[b], e = g_bstart[b + 1];
    long long len = e - s;
    int cs = s + (int)(len * c / POOL_C);
    int ce = s + (int)(len * (c + 1) / POOL_C);
    int d = threadIdx.x;
    float inv = g_consts[1];
    float acc = 0.f;
    for (int n = cs; n < ce; n++) {
        float gv = expf(g_logit[n]) * inv;
        acc += gv * g_h[(size_t)n * DD + d];
        if (d == 0 && out_gate) out_gate[n] = gv;
    }
    g_pool_part[((size_t)b * POOL_C + c) * DD + d] = acc;
}
__global__ void k_pool_red() {
    int b = blockIdx.x, d = threadIdx.x;
    float s = 0.f;
    for (int c = 0; c < POOL_C; c++) s += g_pool_part[((size_t)b * POOL_C + c) * DD + d];
    g_pooled[b * DD + d] = s;
}

// ---------------- final out proj ----------------
__global__ void k_out(const float* __restrict__ W, const float* __restrict__ bias,
                      const float* __restrict__ lg, const float* __restrict__ lb,
                      float* __restrict__ outp) {
    __shared__ float sp[NB * DD];
    __shared__ float sz[NB * DD];
    int t = threadIdx.x;
#pragma unroll
    for (int j = 0; j < 4; j++) sp[t + 256 * j] = g_pooled[t + 256 * j];
    __syncthreads();
    int d = t & 127;
    int b0 = t >> 7;
    float acc[4];
#pragma unroll
    for (int j = 0; j < 4; j++) acc[j] = bias[d];
    for (int k = 0; k < DD; k++) {
        float wv = W[k * DD + d];
#pragma unroll
        for (int j = 0; j < 4; j++) acc[j] += sp[(b0 + 2 * j) * DD + k] * wv;
    }
#pragma unroll
    for (int j = 0; j < 4; j++) sz[(b0 + 2 * j) * DD + d] = acc[j];
    __syncthreads();
    int warp = t >> 5, lane = t & 31;
    float4 v = *reinterpret_cast<float4*>(&sz[warp * DD + lane * 4]);
    float4 u = ln128(v, lg, lb, lane);
    outp[warp * DD + lane * 4 + 0] = geluf(u.x);
    outp[warp * DD + lane * 4 + 1] = geluf(u.y);
    outp[warp * DD + lane * 4 + 2] = geluf(u.z);
    outp[warp * DD + lane * 4 + 3] = geluf(u.w);
}

// ---------------- launch ----------------
extern "C" void kernel_launch(void* const* d_in, const int* in_sizes, int n_in,
                              void* d_out, int out_size) {
    const float* x        = (const float*)d_in[0];
    const int*   ei       = (const int*)d_in[1];
    const int*   batch    = (const int*)d_in[2];
    const float* w_in     = (const float*)d_in[3];
    const float* b_in     = (const float*)d_in[4];
    const float* ln_in_g  = (const float*)d_in[5];
    const float* ln_in_b  = (const float*)d_in[6];
    const float* gnn_w    = (const float*)d_in[7];
    const float* gnn_b    = (const float*)d_in[8];
    const float* gnn_ln_g = (const float*)d_in[9];
    const float* gnn_ln_b = (const float*)d_in[10];
    const float* norm_g   = (const float*)d_in[11];
    const float* norm_b   = (const float*)d_in[12];
    const float* gate_w1  = (const float*)d_in[13];
    const float* gate_b1  = (const float*)d_in[14];
    const float* gate_w2  = (const float*)d_in[15];
    const float* gate_b2  = (const float*)d_in[16];
    const float* out_w    = (const float*)d_in[17];
    const float* out_b    = (const float*)d_in[18];
    const float* out_ln_g = (const float*)d_in[19];
    const float* out_ln_b = (const float*)d_in[20];

    float* out = (float*)d_out;
    float* out_h    = (out_size >= NB * DD + NN * DD) ? out + NB * DD : nullptr;
    float* out_gate = (out_size >= NB * DD + NN * DD + NN) ? out + NB * DD + NN * DD : nullptr;

    cudaFuncSetAttribute((const void*)gemm_mma<64, 0>,
                         cudaFuncAttributeMaxDynamicSharedMemorySize, SMEM_DYN);
    cudaFuncSetAttribute((const void*)gemm_mma<256, 1>,
                         cudaFuncAttributeMaxDynamicSharedMemorySize, SMEM_DYN);
    cudaFuncSetAttribute((const void*)gemm_mma<128, 2>,
                         cudaFuncAttributeMaxDynamicSharedMemorySize, SMEM_DYN);

    const int GT = (NN + 127) / 128;
    const int GW = (NN * 32 + 255) / 256;
    const int GE = (NE + 255) / 256;
    const int GN = (NN + 255) / 256;

    // CSR build
    k_zero<<<GN, 256>>>();
    k_count<<<GE, 256>>>(ei);
    k_scan1<<<NBLK, 256>>>();
    k_scan3<<<NBLK, 256>>>();
    k_scatter<<<GE, 256>>>(ei);

    // weight split (bf16 hi/lo)
    k_split_w<<<(WTOT + 255) / 256, 256>>>(w_in, gnn_w, gate_w1);

    // input projection (+ fused LN->GELU)
    gemm_mma<64, 0><<<GT, 256, SMEM_DYN>>>(x, b_in, ln_in_g, ln_in_b, nullptr, nullptr,
                                           nullptr, 0, 0, NN);

    // GNN layers (+ fused GELU->LN->LN[->GELU+res])
    for (int l = 0; l < NL; l++) {
        k_aggregate<<<GW, 256>>>();
        gemm_mma<256, 1><<<GT, 256, SMEM_DYN>>>(nullptr, gnn_b + l * 128,
                                                gnn_ln_g + l * 128, gnn_ln_b + l * 128,
                                                norm_g + l * 128, norm_b + l * 128,
                                                (l == NL - 1) ? out_h : nullptr,
                                                8192 + l * 32768,
                                                (l < NL - 1) ? 1 : 0, NN);
    }

    // gate (+ fused tanh + dot(w2))
    gemm_mma<128, 2><<<GT, 256, SMEM_DYN>>>(nullptr, gate_b1, gate_w2, nullptr, gate_b2,
                                            nullptr, nullptr, 106496, 0, NN);

    // softmax sum + boundaries
    k_rsum<<<256, 256>>>();
    k_rsum_fin<<<1, 256>>>(batch);

    // pooling (gate inline)
    k_pool<<<NB * POOL_C, 128>>>(out_gate);
    k_pool_red<<<NB, 128>>>();

    // final projection
    k_out<<<1, 256>>>(out_w, out_b, out_ln_g, out_ln_b, out);
}